// round 6
// baseline (speedup 1.0000x reference)
#include <cuda_runtime.h>
#include <cuda_bf16.h>
#include <cstdint>
#include <cstddef>

#define BATCH 4
#define TT    2048
#define CC    1024
#define NEG_INF (__int_as_float(0xff800000))

#define BM 128
#define BN 128
#define BK 32
#define NTH 256

// SMEM: 4 bf16 tiles of 128 rows x 40 (32 + 8 pad) per stage, 2 stages
#define ROWSTR 40
#define TILE_E (128 * ROWSTR)
#define OFF_AH 0
#define OFF_AL (1 * TILE_E)
#define OFF_BH (2 * TILE_E)
#define OFF_BL (3 * TILE_E)
#define STAGE_E (4 * TILE_E)               // 20480 elems = 40960 B
#define SMEM_BYTES (2 * STAGE_E * 2)       // 81920 B

typedef __nv_bfloat16 bf16;

// ---------------- scratch (device globals; allocation-free rule) ------------
__device__ bf16 g_qh[(size_t)BATCH*TT*CC],  g_ql[(size_t)BATCH*TT*CC];
__device__ bf16 g_kh[(size_t)BATCH*TT*CC],  g_kl[(size_t)BATCH*TT*CC];
__device__ bf16 g_vh[(size_t)BATCH*TT*CC],  g_vl[(size_t)BATCH*TT*CC];
__device__ bf16 g_Wqh[CC*CC], g_Wql[CC*CC];
__device__ bf16 g_Wkh[CC*CC], g_Wkl[CC*CC];
__device__ bf16 g_Wvh[CC*CC], g_Wvl[CC*CC];
__device__ bf16 g_Wfh[CC*CC], g_Wfl[CC*CC];
__device__ bf16 g_Qh[(size_t)BATCH*TT*CC],  g_Ql[(size_t)BATCH*TT*CC];
__device__ bf16 g_Kh[(size_t)BATCH*TT*CC],  g_Kl[(size_t)BATCH*TT*CC];
__device__ bf16 g_VTh[(size_t)BATCH*CC*TT], g_VTl[(size_t)BATCH*CC*TT];
__device__ bf16 g_Oh[(size_t)BATCH*TT*CC],  g_Ol[(size_t)BATCH*TT*CC];
__device__ bf16 g_Ph[(size_t)BATCH*TT*TT],  g_Pl[(size_t)BATCH*TT*TT];
__device__ float g_S[(size_t)BATCH*TT*TT];

// ---------------------------------------------------------------------------
__device__ __forceinline__ void mma_bf16(float* d, const uint32_t* a, uint32_t b0, uint32_t b1) {
    asm volatile(
        "mma.sync.aligned.m16n8k16.row.col.f32.bf16.bf16.f32 "
        "{%0,%1,%2,%3},{%4,%5,%6,%7},{%8,%9},{%0,%1,%2,%3};\n"
        : "+f"(d[0]), "+f"(d[1]), "+f"(d[2]), "+f"(d[3])
        : "r"(a[0]), "r"(a[1]), "r"(a[2]), "r"(a[3]), "r"(b0), "r"(b1));
}

#define CP16(dst_u32, src_ptr) \
    asm volatile("cp.async.cg.shared.global [%0], [%1], 16;" :: "r"(dst_u32), "l"(src_ptr))
#define CP_COMMIT() asm volatile("cp.async.commit_group;")
#define CP_WAIT1()  asm volatile("cp.async.wait_group 1;")

__device__ __forceinline__ void split1(float f, bf16& h, bf16& l) {
    h = __float2bfloat16_rn(f);
    l = __float2bfloat16_rn(f - __bfloat162float(h));
}

// ---------------------------------------------------------------------------
// split prepass: fp32 -> bf16 hi/lo, vectorized by 4
__global__ __launch_bounds__(256)
void split_kernel(const float* __restrict__ in, bf16* __restrict__ hi,
                  bf16* __restrict__ lo, int n4)
{
    int i = blockIdx.x * 256 + threadIdx.x;
    if (i >= n4) return;
    float4 f = ((const float4*)in)[i];
    bf16 h0,l0,h1,l1,h2,l2,h3,l3;
    split1(f.x,h0,l0); split1(f.y,h1,l1); split1(f.z,h2,l2); split1(f.w,h3,l3);
    __nv_bfloat162 H0 = {h0,h1}, H1 = {h2,h3}, L0 = {l0,l1}, L1 = {l2,l3};
    ((__nv_bfloat162*)hi)[2*i]   = H0;  ((__nv_bfloat162*)hi)[2*i+1] = H1;
    ((__nv_bfloat162*)lo)[2*i]   = L0;  ((__nv_bfloat162*)lo)[2*i+1] = L1;
}

// ---------------------------------------------------------------------------
// Split-bf16 mma.sync GEMM-NT with pre-split operands and cp.async pipeline.
//   C = alpha * Ah_plus_lo @ B^T (+bias) (+mask); 3-term: AhBh + AhBl + AlBh
// Outputs: if Cf != null -> fp32 row-major; else Ch/Cl bf16 hi/lo
// transC: write C transposed per batch; kvlim: K limited to (by+1)*128
// ---------------------------------------------------------------------------
__global__ __launch_bounds__(NTH, 2)
void gemm_mma(const bf16* __restrict__ Ah, const bf16* __restrict__ Al,
              const bf16* __restrict__ Bh, const bf16* __restrict__ Bl,
              const float* __restrict__ bias,
              float* __restrict__ Cf, bf16* __restrict__ Ch, bf16* __restrict__ Cl,
              int M, int N, int K,
              size_t sA, size_t sB, size_t sC,
              float alpha, int causal, int kvlim, int transC)
{
    const int bx = blockIdx.x, by = blockIdx.y, bz = blockIdx.z;
    if (causal && bx > by) return;
    Ah += (size_t)bz * sA;  Al += (size_t)bz * sA;
    Bh += (size_t)bz * sB;  Bl += (size_t)bz * sB;
    if (Cf) Cf += (size_t)bz * sC;
    if (Ch) { Ch += (size_t)bz * sC; Cl += (size_t)bz * sC; }

    const int m0 = by * BM, n0 = bx * BN;
    const int Keff = kvlim ? (by + 1) * BM : K;
    const int nch  = Keff / BK;

    extern __shared__ bf16 sm[];
    const uint32_t smb = (uint32_t)__cvta_generic_to_shared(sm);

    const int t = threadIdx.x, w = t >> 5, lane = t & 31;
    const int qr = lane >> 2, qc = (lane & 3) * 2;
    const int mb = (w & 1) * 64, nb = (w >> 1) * 32;

    // cp.async geometry: 2 16B-chunks per tile per thread
    const int r0 = (t * 2)     >> 2, c0 = (t * 2)     & 3;
    const int r1 = (t * 2 + 1) >> 2, c1 = (t * 2 + 1) & 3;

    float acc[4][4][4] = {};

    // stage issue: copies chunk i of all 4 tiles into slot i&1
    auto issue = [&](int i) {
        const int k0 = i * BK;
        const uint32_t stg = smb + (uint32_t)((i & 1) * STAGE_E * 2);
        const size_t a0 = (size_t)(m0 + r0) * K + k0 + c0 * 8;
        const size_t a1 = (size_t)(m0 + r1) * K + k0 + c1 * 8;
        const size_t b0 = (size_t)(n0 + r0) * K + k0 + c0 * 8;
        const size_t b1 = (size_t)(n0 + r1) * K + k0 + c1 * 8;
        const uint32_t dA0 = (uint32_t)((r0 * ROWSTR + c0 * 8) * 2);
        const uint32_t dA1 = (uint32_t)((r1 * ROWSTR + c1 * 8) * 2);
        CP16(stg + OFF_AH*2 + dA0, Ah + a0);
        CP16(stg + OFF_AH*2 + dA1, Ah + a1);
        CP16(stg + OFF_AL*2 + dA0, Al + a0);
        CP16(stg + OFF_AL*2 + dA1, Al + a1);
        CP16(stg + OFF_BH*2 + dA0, Bh + b0);
        CP16(stg + OFF_BH*2 + dA1, Bh + b1);
        CP16(stg + OFF_BL*2 + dA0, Bl + b0);
        CP16(stg + OFF_BL*2 + dA1, Bl + b1);
        CP_COMMIT();
    };

    issue(0);
    if (nch > 1) issue(1);

    for (int i = 0; i < nch; i++) {
        CP_WAIT1();
        __syncthreads();
        const bf16* stg = sm + (i & 1) * STAGE_E;
#pragma unroll
        for (int kk = 0; kk < BK; kk += 16) {
            uint32_t bhf[4][2], blf[4][2];
#pragma unroll
            for (int j = 0; j < 4; j++) {
                const int nr = nb + j * 8 + qr;
                bhf[j][0] = *(const uint32_t*)&stg[OFF_BH + nr * ROWSTR + kk + qc];
                bhf[j][1] = *(const uint32_t*)&stg[OFF_BH + nr * ROWSTR + kk + qc + 8];
                blf[j][0] = *(const uint32_t*)&stg[OFF_BL + nr * ROWSTR + kk + qc];
                blf[j][1] = *(const uint32_t*)&stg[OFF_BL + nr * ROWSTR + kk + qc + 8];
            }
#pragma unroll
            for (int ii = 0; ii < 4; ii++) {
                const int ar = mb + ii * 16 + qr;
                uint32_t ah[4], al[4];
                ah[0] = *(const uint32_t*)&stg[OFF_AH + ar * ROWSTR + kk + qc];
                ah[1] = *(const uint32_t*)&stg[OFF_AH + (ar + 8) * ROWSTR + kk + qc];
                ah[2] = *(const uint32_t*)&stg[OFF_AH + ar * ROWSTR + kk + qc + 8];
                ah[3] = *(const uint32_t*)&stg[OFF_AH + (ar + 8) * ROWSTR + kk + qc + 8];
                al[0] = *(const uint32_t*)&stg[OFF_AL + ar * ROWSTR + kk + qc];
                al[1] = *(const uint32_t*)&stg[OFF_AL + (ar + 8) * ROWSTR + kk + qc];
                al[2] = *(const uint32_t*)&stg[OFF_AL + ar * ROWSTR + kk + qc + 8];
                al[3] = *(const uint32_t*)&stg[OFF_AL + (ar + 8) * ROWSTR + kk + qc + 8];
#pragma unroll
                for (int j = 0; j < 4; j++) {
                    mma_bf16(acc[ii][j], ah, bhf[j][0], bhf[j][1]);
                    mma_bf16(acc[ii][j], ah, blf[j][0], blf[j][1]);
                    mma_bf16(acc[ii][j], al, bhf[j][0], bhf[j][1]);
                }
            }
        }
        __syncthreads();
        if (i + 2 < nch) issue(i + 2);
    }

    // ---- epilogue
    const int diag = (causal && bx == by);
#pragma unroll
    for (int ii = 0; ii < 4; ii++) {
#pragma unroll
        for (int j = 0; j < 4; j++) {
            const int rA = m0 + mb + ii * 16 + qr;
            const int rB = rA + 8;
            const int cb = n0 + nb + j * 8 + qc;
            float v00 = acc[ii][j][0] * alpha, v01 = acc[ii][j][1] * alpha;
            float v10 = acc[ii][j][2] * alpha, v11 = acc[ii][j][3] * alpha;
            if (bias) {
                const float b0 = bias[cb], b1 = bias[cb + 1];
                v00 += b0; v01 += b1; v10 += b0; v11 += b1;
            }
            if (diag) {
                if (cb     > rA) v00 = NEG_INF;
                if (cb + 1 > rA) v01 = NEG_INF;
                if (cb     > rB) v10 = NEG_INF;
                if (cb + 1 > rB) v11 = NEG_INF;
            }
            if (Cf) {
                *(float2*)&Cf[(size_t)rA * N + cb] = make_float2(v00, v01);
                *(float2*)&Cf[(size_t)rB * N + cb] = make_float2(v10, v11);
            } else if (transC) {
                const size_t bo = (size_t)(rA >> 11) * ((size_t)CC * TT);
                const int mA = rA & (TT - 1), mB = rB & (TT - 1);
                bf16 h, l;
                split1(v00, h, l); Ch[bo + (size_t)cb*TT + mA] = h; Cl[bo + (size_t)cb*TT + mA] = l;
                split1(v01, h, l); Ch[bo + (size_t)(cb+1)*TT + mA] = h; Cl[bo + (size_t)(cb+1)*TT + mA] = l;
                split1(v10, h, l); Ch[bo + (size_t)cb*TT + mB] = h; Cl[bo + (size_t)cb*TT + mB] = l;
                split1(v11, h, l); Ch[bo + (size_t)(cb+1)*TT + mB] = h; Cl[bo + (size_t)(cb+1)*TT + mB] = l;
            } else {
                bf16 h0,l0,h1,l1;
                split1(v00,h0,l0); split1(v01,h1,l1);
                *(__nv_bfloat162*)&Ch[(size_t)rA*N + cb] = __nv_bfloat162{h0,h1};
                *(__nv_bfloat162*)&Cl[(size_t)rA*N + cb] = __nv_bfloat162{l0,l1};
                split1(v10,h0,l0); split1(v11,h1,l1);
                *(__nv_bfloat162*)&Ch[(size_t)rB*N + cb] = __nv_bfloat162{h0,h1};
                *(__nv_bfloat162*)&Cl[(size_t)rB*N + cb] = __nv_bfloat162{l0,l1};
            }
        }
    }
}

// ---------------------------------------------------------------------------
// Row softmax over fp32 S; writes bf16 hi/lo probability arrays.
// Valid length = ((row>>7)+1)*128.
// ---------------------------------------------------------------------------
__global__ __launch_bounds__(256)
void softmax_kernel(const float* __restrict__ S, bf16* __restrict__ Ph,
                    bf16* __restrict__ Pl)
{
    const int row = blockIdx.x;
    const int b   = blockIdx.y;
    const size_t base = ((size_t)b * TT + row) * TT;
    const float* Sr = S + base;
    const int ncols = ((row >> 7) + 1) << 7;
    const int t = threadIdx.x;

    __shared__ float red[256];

    float mx = NEG_INF;
    for (int c = t; c < ncols; c += 256) mx = fmaxf(mx, Sr[c]);
    red[t] = mx;
    __syncthreads();
    for (int s = 128; s > 0; s >>= 1) {
        if (t < s) red[t] = fmaxf(red[t], red[t + s]);
        __syncthreads();
    }
    mx = red[0];
    __syncthreads();

    float sum = 0.0f;
    // cache exp values in registers impossible (var length); recompute on 2nd pass
    for (int c = t; c < ncols; c += 256) sum += expf(Sr[c] - mx);
    red[t] = sum;
    __syncthreads();
    for (int s = 128; s > 0; s >>= 1) {
        if (t < s) red[t] += red[t + s];
        __syncthreads();
    }
    const float inv = 1.0f / red[0];

    for (int c = t; c < ncols; c += 256) {
        float p = expf(Sr[c] - mx) * inv;
        bf16 h, l;
        split1(p, h, l);
        Ph[base + c] = h;
        Pl[base + c] = l;
    }
    // zero-fill the rest of the row's last 128-block? not needed: ncols is a
    // multiple of 128 and GEMM kvlim never reads beyond (rowblk+1)*128.
}

// ---------------------------------------------------------------------------
extern "C" void kernel_launch(void* const* d_in, const int* in_sizes, int n_in,
                              void* d_out, int out_size)
{
    const float* q   = (const float*)d_in[0];
    const float* k   = (const float*)d_in[1];
    const float* v   = (const float*)d_in[2];
    const float* Wq  = (const float*)d_in[3];
    const float* bq  = (const float*)d_in[4];
    const float* Wk  = (const float*)d_in[5];
    const float* bk  = (const float*)d_in[6];
    const float* Wv  = (const float*)d_in[7];
    const float* bv  = (const float*)d_in[8];
    const float* Wff = (const float*)d_in[9];
    const float* bff = (const float*)d_in[10];
    float* out = (float*)d_out;

    bf16 *qh,*ql,*kh,*kl,*vh,*vl,*Wqh,*Wql,*Wkh,*Wkl,*Wvh,*Wvl,*Wfh,*Wfl;
    bf16 *Qh,*Ql,*Kh,*Kl,*VTh,*VTl,*Oh,*Ol,*Ph,*Pl;
    float* S;
    cudaGetSymbolAddress((void**)&qh, g_qh);   cudaGetSymbolAddress((void**)&ql, g_ql);
    cudaGetSymbolAddress((void**)&kh, g_kh);   cudaGetSymbolAddress((void**)&kl, g_kl);
    cudaGetSymbolAddress((void**)&vh, g_vh);   cudaGetSymbolAddress((void**)&vl, g_vl);
    cudaGetSymbolAddress((void**)&Wqh, g_Wqh); cudaGetSymbolAddress((void**)&Wql, g_Wql);
    cudaGetSymbolAddress((void**)&Wkh, g_Wkh); cudaGetSymbolAddress((void**)&Wkl, g_Wkl);
    cudaGetSymbolAddress((void**)&Wvh, g_Wvh); cudaGetSymbolAddress((void**)&Wvl, g_Wvl);
    cudaGetSymbolAddress((void**)&Wfh, g_Wfh); cudaGetSymbolAddress((void**)&Wfl, g_Wfl);
    cudaGetSymbolAddress((void**)&Qh, g_Qh);   cudaGetSymbolAddress((void**)&Ql, g_Ql);
    cudaGetSymbolAddress((void**)&Kh, g_Kh);   cudaGetSymbolAddress((void**)&Kl, g_Kl);
    cudaGetSymbolAddress((void**)&VTh, g_VTh); cudaGetSymbolAddress((void**)&VTl, g_VTl);
    cudaGetSymbolAddress((void**)&Oh, g_Oh);   cudaGetSymbolAddress((void**)&Ol, g_Ol);
    cudaGetSymbolAddress((void**)&Ph, g_Ph);   cudaGetSymbolAddress((void**)&Pl, g_Pl);
    cudaGetSymbolAddress((void**)&S,  g_S);

    cudaFuncSetAttribute(gemm_mma, cudaFuncAttributeMaxDynamicSharedMemorySize, SMEM_BYTES);

    const int M = BATCH * TT;          // 8192
    const int NQ4 = (M * CC) / 4;      // input splits
    const int NW4 = (CC * CC) / 4;

    // 0) split raw inputs into bf16 hi/lo
    split_kernel<<<(NQ4 + 255)/256, 256>>>(q, qh, ql, NQ4);
    split_kernel<<<(NQ4 + 255)/256, 256>>>(k, kh, kl, NQ4);
    split_kernel<<<(NQ4 + 255)/256, 256>>>(v, vh, vl, NQ4);
    split_kernel<<<(NW4 + 255)/256, 256>>>(Wq, Wqh, Wql, NW4);
    split_kernel<<<(NW4 + 255)/256, 256>>>(Wk, Wkh, Wkl, NW4);
    split_kernel<<<(NW4 + 255)/256, 256>>>(Wv, Wvh, Wvl, NW4);
    split_kernel<<<(NW4 + 255)/256, 256>>>(Wff, Wfh, Wfl, NW4);

    const dim3 blk(NTH);

    // 1) Projections (outputs stay split; V transposed)
    gemm_mma<<<dim3(CC/BN, M/BM, 1), blk, SMEM_BYTES>>>(
        qh, ql, Wqh, Wql, bq, nullptr, Qh, Ql,
        M, CC, CC, 0, 0, 0, 1.0f, 0, 0, 0);
    gemm_mma<<<dim3(CC/BN, M/BM, 1), blk, SMEM_BYTES>>>(
        kh, kl, Wkh, Wkl, bk, nullptr, Kh, Kl,
        M, CC, CC, 0, 0, 0, 1.0f, 0, 0, 0);
    gemm_mma<<<dim3(CC/BN, M/BM, 1), blk, SMEM_BYTES>>>(
        vh, vl, Wvh, Wvl, bv, nullptr, VTh, VTl,
        M, CC, CC, 0, 0, 0, 1.0f, 0, 0, 1);

    // 2) Scores -> fp32 S (causal lower-tri blocks only)
    gemm_mma<<<dim3(TT/BN, TT/BM, BATCH), blk, SMEM_BYTES>>>(
        Qh, Ql, Kh, Kl, nullptr, S, nullptr, nullptr,
        TT, TT, CC, (size_t)TT*CC, (size_t)TT*CC, (size_t)TT*TT,
        1.0f/32.0f, 1, 0, 0);

    // 3) softmax -> split probabilities
    softmax_kernel<<<dim3(TT, BATCH), dim3(256)>>>(S, Ph, Pl);

    // 4) O = P @ V (NT vs transposed V, causal K-limit) -> split O
    gemm_mma<<<dim3(CC/BN, TT/BM, BATCH), blk, SMEM_BYTES>>>(
        Ph, Pl, VTh, VTl, nullptr, nullptr, Oh, Ol,
        TT, CC, TT, (size_t)TT*TT, (size_t)CC*TT, (size_t)TT*CC,
        1.0f, 0, 1, 0);

    // 5) final projection -> fp32 out
    gemm_mma<<<dim3(CC/BN, M/BM, 1), blk, SMEM_BYTES>>>(
        Oh, Ol, Wfh, Wfl, bff, out, nullptr, nullptr,
        M, CC, CC, 0, 0, 0, 1.0f, 0, 0, 0);
}